// round 15
// baseline (speedup 1.0000x reference)
#include <cuda_runtime.h>

typedef unsigned long long ull;

// ---------------- packed f32x2 helpers (Blackwell) ----------------
__device__ __forceinline__ ull bc2(float f) {
    ull r; asm("mov.b64 %0, {%1, %1};" : "=l"(r) : "f"(f)); return r;
}
__device__ __forceinline__ ull pk2(float a, float b) {
    ull r; asm("mov.b64 %0, {%1, %2};" : "=l"(r) : "f"(a), "f"(b)); return r;
}
__device__ __forceinline__ float2 up2(ull u) {
    float2 v; asm("mov.b64 {%0, %1}, %2;" : "=f"(v.x), "=f"(v.y) : "l"(u)); return v;
}
__device__ __forceinline__ ull mul2(ull a, ull b) {
    ull r; asm("mul.rn.f32x2 %0, %1, %2;" : "=l"(r) : "l"(a), "l"(b)); return r;
}
__device__ __forceinline__ ull fma2(ull a, ull b, ull c) {
    ull r; asm("fma.rn.f32x2 %0, %1, %2, %3;" : "=l"(r) : "l"(a), "l"(b), "l"(c)); return r;
}

// mbarrier wait on phase parity — documented suspend-time form (HW sleep).
__device__ __forceinline__ void mbar_wait(unsigned mb, unsigned phase) {
    unsigned done;
    asm volatile(
        "{\n\t.reg .pred p;\n\t"
        "mbarrier.try_wait.parity.acquire.cta.shared::cta.b64 p, [%1], %2;\n\t"
        "selp.b32 %0, 1, 0, p;\n\t}"
        : "=r"(done) : "r"(mb), "r"(phase) : "memory");
    if (!done) {
        asm volatile(
            "{\n\t.reg .pred P1;\n\t"
            "W_%=:\n\t"
            "mbarrier.try_wait.parity.acquire.cta.shared::cta.b64 P1, [%0], %1, 0x989680;\n\t"
            "@P1 bra D_%=;\n\t"
            "bra.uni W_%=;\n\t"
            "D_%=:\n\t}"
            :: "r"(mb), "r"(phase) : "memory");
    }
}

// q-index into a stage's [512][2][2] twiddle table for element pair (p, p+s).
__device__ __forceinline__ int qidx(int p, int ls) {
    int s = 1 << ls;
    return ((p >> (ls + 1)) << ls) | (p & (s - 1));
}

// Transpose padding 1/8 at float4 granularity (patterns verified mod-32).
__device__ __forceinline__ int phys(int p) { return p + (p >> 3); }

// O2 ownership: element index for thread t, slot e.
__device__ __forceinline__ int o2p(int t, int e) {
    return (t & 7) | (e << 3) | ((t >> 3) << 6);
}

static const int NGROUPS_TOTAL = 8192;   // 32768 rows / 4 per group (2 row-pairs)
static const int GRID = 296;             // 148 SMs x 2 CTAs
static const int BASE_PER_BLK = NGROUPS_TOTAL / GRID;   // 27
static const int EXTRA_BLKS   = NGROUPS_TOTAL % GRID;   // 200

// dynamic smem layout (104512 B/CTA; 2 CTAs/SM -> 209 KB < 228 KB):
//   [0,      18432)  bufT1: [1152] float4 (WARP-PRIVATE regions; syncwarp only)
//   [18432,  55296)  bufT2: [2][1152] float4 (double-buffered; CTA barrier)
//   [55296, 104448)  input staging: 3 buffers x 16384 B
//   [104448,104472)  3 mbarriers
static const int BUF_F4   = 1152;
static const int BUF2_OFF = BUF_F4 * 16;                 // 18432
static const int XIN_OFF  = BUF2_OFF + 2 * BUF_F4 * 16;  // 55296
static const int MBAR_OFF = XIN_OFF + 3 * 16384;         // 104448
static const int SMEM_DYN = MBAR_OFF + 64;               // 104512

// ---------------- persistent main kernel ----------------
// Stage schedule: O1 intra(1,2,4) -> T1[warp-local] -> O2 intra(8,16,32) ->
// shfl^8 (stage 64) -> T2[CTA, double-buffered, ONE barrier/iter] ->
// O3 intra(128,256,512) with bias folded into the last stage.
// R15: contiguous group chunks per block (sequential 16KB DRAM bursts),
// rotated TMA-issuing thread (removes the warp-0 systematic straggler),
// bias folded into O3's final fma.
__global__ void __launch_bounds__(128, 2) butterfly_main(
    const float* __restrict__ x,
    const float* __restrict__ tw,       // [10][512][2][2]
    const float* __restrict__ bias,
    float* __restrict__ out)
{
    extern __shared__ char smem_raw[];
    float4* bufT1 = reinterpret_cast<float4*>(smem_raw);               // [1152]
    float4* bufT2 = reinterpret_cast<float4*>(smem_raw + BUF2_OFF);    // [2][1152]
    float4* xin   = reinterpret_cast<float4*>(smem_raw + XIN_OFF);     // [3][1024]
    const unsigned mbar_base = (unsigned)__cvta_generic_to_shared(smem_raw + MBAR_OFF);
    const unsigned xin_base  = (unsigned)__cvta_generic_to_shared(smem_raw + XIN_OFF);

    const int t = threadIdx.x;
    const float4* tw4 = reinterpret_cast<const float4*>(tw);  // [10][512] float4

    // ---- contiguous chunk for this block ----
    const int b   = blockIdx.x;
    const int lo  = b * BASE_PER_BLK + (b < EXTRA_BLKS ? b : EXTRA_BLKS);
    const int cnt = BASE_PER_BLK + (b < EXTRA_BLKS ? 1 : 0);
    const int hi  = lo + cnt;

    // ---- one-time twiddle load + repack into registers (160 floats) ----
    float tA[3][4][4];   // O1 stages 1,2,4:    [ls][j][t00,t01,t10,t11]
    float tB[3][4][4];   // O2 stages 8,16,32:  [ls-3][j][t00,t01,t10,t11]
    float tS[8][2];      // shfl stage 64:      [e][ta,tb]
    float tC[3][4][4];   // O3 stages 128..512: [ls-7][j][t00,t01,t10,t11]

    #pragma unroll
    for (int ls = 0; ls < 3; ls++) {
        const int s = 1 << ls;
        #pragma unroll
        for (int j = 0; j < 4; j++) {
            int eL = ((j >> ls) << (ls + 1)) | (j & (s - 1));
            float4 w = tw4[ls * 512 + qidx(8 * t + eL, ls)];
            tA[ls][j][0] = w.x; tA[ls][j][1] = w.y; tA[ls][j][2] = w.z; tA[ls][j][3] = w.w;
        }
    }
    #pragma unroll
    for (int ls = 3; ls < 6; ls++) {
        const int sig = 1 << (ls - 3);
        #pragma unroll
        for (int j = 0; j < 4; j++) {
            int eL = ((j >> (ls - 3)) << (ls - 3 + 1)) | (j & (sig - 1));
            float4 w = tw4[ls * 512 + qidx(o2p(t, eL), ls)];
            tB[ls-3][j][0] = w.x; tB[ls-3][j][1] = w.y; tB[ls-3][j][2] = w.z; tB[ls-3][j][3] = w.w;
        }
    }
    {
        const int i = (t >> 3) & 1;   // bit 6 of o2p = bit 3 of t
        #pragma unroll
        for (int e = 0; e < 8; e++) {
            float4 w = tw4[6 * 512 + qidx(o2p(t, e), 6)];
            tS[e][0] = i ? w.w : w.x;
            tS[e][1] = i ? w.z : w.y;
        }
    }
    #pragma unroll
    for (int ls = 7; ls < 10; ls++) {
        const int sig = 1 << (ls - 7);
        #pragma unroll
        for (int j = 0; j < 4; j++) {
            int eL = ((j >> (ls - 7)) << (ls - 7 + 1)) | (j & (sig - 1));
            float4 w = tw4[ls * 512 + qidx(t + 128 * eL, ls)];
            tC[ls-7][j][0] = w.x; tC[ls-7][j][1] = w.y; tC[ls-7][j][2] = w.z; tC[ls-7][j][3] = w.w;
        }
    }

    // packed bias for O3 ownership p = t + 128e (folded into O3's last stage)
    ull bv2[8];
    #pragma unroll
    for (int e = 0; e < 8; e++) bv2[e] = bc2(bias[t + 128 * e]);

    // ---- mbarrier init (count=1: one elected thread arrives) ----
    if (t == 0) {
        #pragma unroll
        for (int bb = 0; bb < 3; bb++)
            asm volatile("mbarrier.init.shared::cta.b64 [%0], 1;"
                         :: "r"(mbar_base + bb * 8) : "memory");
    }
    __syncthreads();

    // ---- bulk staging: one 16KB cp.async.bulk per group; the issuing
    // thread rotates across warps (t = (gg&3)*32) so no single warp is a
    // systematic straggler at the CTA barrier ----
    auto stage = [&](int gg, int bb) {
        if (gg < hi && t == ((gg & 3) << 5)) {
            unsigned mb = mbar_base + bb * 8;
            asm volatile("mbarrier.arrive.expect_tx.shared::cta.b64 _, [%0], %1;"
                         :: "r"(mb), "r"(16384) : "memory");
            asm volatile(
                "cp.async.bulk.shared::cta.global.mbarrier::complete_tx::bytes "
                "[%0], [%1], %2, [%3];"
                :: "r"(xin_base + bb * 16384),
                   "l"(x + (size_t)gg * 4096),
                   "r"(16384), "r"(mb) : "memory");
        }
    };

    // ---- prologue: stage first two groups (prefetch distance 2) ----
    stage(lo,     0);
    stage(lo + 1, 1);

    int par = 0, phase = 0, db = 0;
    for (int g = lo; g < hi; ++g) {
        int nb = par + 2; if (nb >= 3) nb -= 3;
        stage(g + 2, nb);

        // wait for this group's bulk copy to land
        mbar_wait(mbar_base + par * 8, phase);

        // input unpack (linear layout: row r at offset r*4KB); O1 ownership
        ull D[2][8];
        #pragma unroll
        for (int c = 0; c < 2; c++) {
            const float4* s0 = &xin[(par * 4 + 2 * c    ) * 256 + 2 * t];
            const float4* s1 = &xin[(par * 4 + 2 * c + 1) * 256 + 2 * t];
            float4 a0 = s0[0], a1 = s0[1];
            float4 b0 = s1[0], b1 = s1[1];
            D[c][0] = pk2(a0.x, b0.x);  D[c][1] = pk2(a0.y, b0.y);
            D[c][2] = pk2(a0.z, b0.z);  D[c][3] = pk2(a0.w, b0.w);
            D[c][4] = pk2(a1.x, b1.x);  D[c][5] = pk2(a1.y, b1.y);
            D[c][6] = pk2(a1.z, b1.z);  D[c][7] = pk2(a1.w, b1.w);
        }
        if (++par >= 3) { par = 0; phase ^= 1; }

        // O1: stages 1,2,4 (intra-thread, e bits 0-2)
        #pragma unroll
        for (int ls = 0; ls < 3; ls++) {
            const int s = 1 << ls;
            #pragma unroll
            for (int j = 0; j < 4; j++) {
                const int eL = ((j >> ls) << (ls + 1)) | (j & (s - 1));
                const int eH = eL + s;
                ull t00 = bc2(tA[ls][j][0]), t01 = bc2(tA[ls][j][1]);
                ull t10 = bc2(tA[ls][j][2]), t11 = bc2(tA[ls][j][3]);
                #pragma unroll
                for (int c = 0; c < 2; c++) {
                    ull x0 = D[c][eL], x1 = D[c][eH];
                    D[c][eL] = fma2(t00, x0, mul2(t01, x1));
                    D[c][eH] = fma2(t10, x0, mul2(t11, x1));
                }
            }
        }

        // ---- transpose 1: WARP-LOCAL (bufT1 region per warp is private) ----
        #pragma unroll
        for (int e = 0; e < 8; e++) {
            int p = 8 * t + e;
            float2 v0 = up2(D[0][e]), v1 = up2(D[1][e]);
            bufT1[phys(p)] = make_float4(v0.x, v0.y, v1.x, v1.y);
        }
        __syncwarp();
        #pragma unroll
        for (int e = 0; e < 8; e++) {
            float4 f = bufT1[phys(o2p(t, e))];
            D[0][e] = pk2(f.x, f.y);
            D[1][e] = pk2(f.z, f.w);
        }

        // O2: stages 8,16,32 (intra-thread, e bits = p bits 3-5)
        #pragma unroll
        for (int ls = 3; ls < 6; ls++) {
            const int sig = 1 << (ls - 3);
            #pragma unroll
            for (int j = 0; j < 4; j++) {
                const int eL = ((j >> (ls - 3)) << (ls - 3 + 1)) | (j & (sig - 1));
                const int eH = eL + sig;
                ull t00 = bc2(tB[ls-3][j][0]), t01 = bc2(tB[ls-3][j][1]);
                ull t10 = bc2(tB[ls-3][j][2]), t11 = bc2(tB[ls-3][j][3]);
                #pragma unroll
                for (int c = 0; c < 2; c++) {
                    ull x0 = D[c][eL], x1 = D[c][eH];
                    D[c][eL] = fma2(t00, x0, mul2(t01, x1));
                    D[c][eH] = fma2(t10, x0, mul2(t11, x1));
                }
            }
        }

        // stage 64: ONE shfl stage (p bit 6 = t bit 3 -> lane^8)
        #pragma unroll
        for (int c = 0; c < 2; c++)
            #pragma unroll
            for (int e = 0; e < 8; e++) {
                ull o = __shfl_xor_sync(0xffffffffu, D[c][e], 8);
                D[c][e] = fma2(bc2(tS[e][0]), D[c][e], mul2(bc2(tS[e][1]), o));
            }

        // ---- transpose 2: CTA-wide, double-buffered, single barrier ----
        float4* tb2 = bufT2 + db * BUF_F4;
        #pragma unroll
        for (int e = 0; e < 8; e++) {
            float2 v0 = up2(D[0][e]), v1 = up2(D[1][e]);
            tb2[phys(o2p(t, e))] = make_float4(v0.x, v0.y, v1.x, v1.y);
        }
        __syncthreads();                     // the ONLY CTA barrier per iter
        #pragma unroll
        for (int e = 0; e < 8; e++) {
            float4 f = tb2[phys(t + 128 * e)];
            D[0][e] = pk2(f.x, f.y);
            D[1][e] = pk2(f.z, f.w);
        }
        db ^= 1;

        // O3: stages 128,256 (intra-thread, e bits = p bits 7-9)
        #pragma unroll
        for (int ls = 7; ls < 9; ls++) {
            const int sig = 1 << (ls - 7);
            #pragma unroll
            for (int j = 0; j < 4; j++) {
                const int eL = ((j >> (ls - 7)) << (ls - 7 + 1)) | (j & (sig - 1));
                const int eH = eL + sig;
                ull t00 = bc2(tC[ls-7][j][0]), t01 = bc2(tC[ls-7][j][1]);
                ull t10 = bc2(tC[ls-7][j][2]), t11 = bc2(tC[ls-7][j][3]);
                #pragma unroll
                for (int c = 0; c < 2; c++) {
                    ull x0 = D[c][eL], x1 = D[c][eH];
                    D[c][eL] = fma2(t00, x0, mul2(t01, x1));
                    D[c][eH] = fma2(t10, x0, mul2(t11, x1));
                }
            }
        }
        // final stage 512 with bias folded into the inner fma
        {
            #pragma unroll
            for (int j = 0; j < 4; j++) {
                const int eL = j;            // sig=4: eL = j, eH = j+4
                const int eH = j + 4;
                ull t00 = bc2(tC[2][j][0]), t01 = bc2(tC[2][j][1]);
                ull t10 = bc2(tC[2][j][2]), t11 = bc2(tC[2][j][3]);
                #pragma unroll
                for (int c = 0; c < 2; c++) {
                    ull x0 = D[c][eL], x1 = D[c][eH];
                    D[c][eL] = fma2(t00, x0, fma2(t01, x1, bv2[eL]));
                    D[c][eH] = fma2(t10, x0, fma2(t11, x1, bv2[eH]));
                }
            }
        }

        // epilogue: coalesced streaming stores (bias already applied)
        #pragma unroll
        for (int c = 0; c < 2; c++) {
            float* o0 = out + (size_t)(g * 4 + 2 * c    ) * 1024;
            float* o1 = out + (size_t)(g * 4 + 2 * c + 1) * 1024;
            #pragma unroll
            for (int e = 0; e < 8; e++) {
                float2 v = up2(D[c][e]);
                int p = t + 128 * e;
                __stcs(o0 + p, v.x);
                __stcs(o1 + p, v.y);
            }
        }
    }
}

extern "C" void kernel_launch(void* const* d_in, const int* in_sizes, int n_in,
                              void* d_out, int out_size) {
    const float* x    = (const float*)d_in[0];   // [32768, 1024]
    const float* tw   = (const float*)d_in[1];   // [1,1,10,512,2,2]
    const float* bias = (const float*)d_in[2];   // [1024]
    float* out = (float*)d_out;

    cudaFuncSetAttribute(butterfly_main,
                         cudaFuncAttributeMaxDynamicSharedMemorySize, SMEM_DYN);
    butterfly_main<<<GRID, 128, SMEM_DYN>>>(x, tw, bias, out);
}

// round 16
// speedup vs baseline: 1.0385x; 1.0385x over previous
#include <cuda_runtime.h>

typedef unsigned long long ull;

// ---------------- packed f32x2 helpers (Blackwell) ----------------
__device__ __forceinline__ ull bc2(float f) {
    ull r; asm("mov.b64 %0, {%1, %1};" : "=l"(r) : "f"(f)); return r;
}
__device__ __forceinline__ ull pk2(float a, float b) {
    ull r; asm("mov.b64 %0, {%1, %2};" : "=l"(r) : "f"(a), "f"(b)); return r;
}
__device__ __forceinline__ float2 up2(ull u) {
    float2 v; asm("mov.b64 {%0, %1}, %2;" : "=f"(v.x), "=f"(v.y) : "l"(u)); return v;
}
__device__ __forceinline__ ull mul2(ull a, ull b) {
    ull r; asm("mul.rn.f32x2 %0, %1, %2;" : "=l"(r) : "l"(a), "l"(b)); return r;
}
__device__ __forceinline__ ull fma2(ull a, ull b, ull c) {
    ull r; asm("fma.rn.f32x2 %0, %1, %2, %3;" : "=l"(r) : "l"(a), "l"(b), "l"(c)); return r;
}

// mbarrier wait on phase parity — documented suspend-time form (HW sleep).
__device__ __forceinline__ void mbar_wait(unsigned mb, unsigned phase) {
    unsigned done;
    asm volatile(
        "{\n\t.reg .pred p;\n\t"
        "mbarrier.try_wait.parity.acquire.cta.shared::cta.b64 p, [%1], %2;\n\t"
        "selp.b32 %0, 1, 0, p;\n\t}"
        : "=r"(done) : "r"(mb), "r"(phase) : "memory");
    if (!done) {
        asm volatile(
            "{\n\t.reg .pred P1;\n\t"
            "W_%=:\n\t"
            "mbarrier.try_wait.parity.acquire.cta.shared::cta.b64 P1, [%0], %1, 0x989680;\n\t"
            "@P1 bra D_%=;\n\t"
            "bra.uni W_%=;\n\t"
            "D_%=:\n\t}"
            :: "r"(mb), "r"(phase) : "memory");
    }
}

// q-index into a stage's [512][2][2] twiddle table for element pair (p, p+s).
__device__ __forceinline__ int qidx(int p, int ls) {
    int s = 1 << ls;
    return ((p >> (ls + 1)) << ls) | (p & (s - 1));
}

// Transpose padding 1/8 at float4 granularity (patterns verified mod-32).
__device__ __forceinline__ int phys(int p) { return p + (p >> 3); }

// O2 ownership: element index for thread t, slot e.
__device__ __forceinline__ int o2p(int t, int e) {
    return (t & 7) | (e << 3) | ((t >> 3) << 6);
}

static const int NGROUPS_TOTAL = 8192;   // 32768 rows / 4 per group (2 row-pairs)
static const int GRID = 296;             // 148 SMs x 2 CTAs

// dynamic smem layout (104512 B/CTA; 2 CTAs/SM -> 209 KB < 228 KB):
//   [0,      18432)  bufT1: [1152] float4 (WARP-PRIVATE regions; syncwarp only)
//   [18432,  55296)  bufT2: [2][1152] float4 (double-buffered; CTA barrier)
//   [55296, 104448)  input staging: 3 buffers x 16384 B
//   [104448,104472)  3 mbarriers
static const int BUF_F4   = 1152;
static const int BUF2_OFF = BUF_F4 * 16;                 // 18432
static const int XIN_OFF  = BUF2_OFF + 2 * BUF_F4 * 16;  // 55296
static const int MBAR_OFF = XIN_OFF + 3 * 16384;         // 104448
static const int SMEM_DYN = MBAR_OFF + 64;               // 104512

// ---------------- persistent main kernel ----------------
// R16 = R14 (best family: INTERLEAVED group walk g += GRID — load-bearing for
// DRAM/L2 spread, per the R15 regression — fixed t==0 TMA issuer, warp-local
// T1, double-buffered T2 with ONE CTA barrier/iter) + the single safe piece
// of R15: bias folded into O3's final stage (-16 add2/thread/iter).
__global__ void __launch_bounds__(128, 2) butterfly_main(
    const float* __restrict__ x,
    const float* __restrict__ tw,       // [10][512][2][2]
    const float* __restrict__ bias,
    float* __restrict__ out)
{
    extern __shared__ char smem_raw[];
    float4* bufT1 = reinterpret_cast<float4*>(smem_raw);               // [1152]
    float4* bufT2 = reinterpret_cast<float4*>(smem_raw + BUF2_OFF);    // [2][1152]
    float4* xin   = reinterpret_cast<float4*>(smem_raw + XIN_OFF);     // [3][1024]
    const unsigned mbar_base = (unsigned)__cvta_generic_to_shared(smem_raw + MBAR_OFF);
    const unsigned xin_base  = (unsigned)__cvta_generic_to_shared(smem_raw + XIN_OFF);

    const int t = threadIdx.x;
    const float4* tw4 = reinterpret_cast<const float4*>(tw);  // [10][512] float4

    // ---- one-time twiddle load + repack into registers (160 floats) ----
    float tA[3][4][4];   // O1 stages 1,2,4:    [ls][j][t00,t01,t10,t11]
    float tB[3][4][4];   // O2 stages 8,16,32:  [ls-3][j][t00,t01,t10,t11]
    float tS[8][2];      // shfl stage 64:      [e][ta,tb]
    float tC[3][4][4];   // O3 stages 128..512: [ls-7][j][t00,t01,t10,t11]

    #pragma unroll
    for (int ls = 0; ls < 3; ls++) {
        const int s = 1 << ls;
        #pragma unroll
        for (int j = 0; j < 4; j++) {
            int eL = ((j >> ls) << (ls + 1)) | (j & (s - 1));
            float4 w = tw4[ls * 512 + qidx(8 * t + eL, ls)];
            tA[ls][j][0] = w.x; tA[ls][j][1] = w.y; tA[ls][j][2] = w.z; tA[ls][j][3] = w.w;
        }
    }
    #pragma unroll
    for (int ls = 3; ls < 6; ls++) {
        const int sig = 1 << (ls - 3);
        #pragma unroll
        for (int j = 0; j < 4; j++) {
            int eL = ((j >> (ls - 3)) << (ls - 3 + 1)) | (j & (sig - 1));
            float4 w = tw4[ls * 512 + qidx(o2p(t, eL), ls)];
            tB[ls-3][j][0] = w.x; tB[ls-3][j][1] = w.y; tB[ls-3][j][2] = w.z; tB[ls-3][j][3] = w.w;
        }
    }
    {
        const int i = (t >> 3) & 1;   // bit 6 of o2p = bit 3 of t
        #pragma unroll
        for (int e = 0; e < 8; e++) {
            float4 w = tw4[6 * 512 + qidx(o2p(t, e), 6)];
            tS[e][0] = i ? w.w : w.x;
            tS[e][1] = i ? w.z : w.y;
        }
    }
    #pragma unroll
    for (int ls = 7; ls < 10; ls++) {
        const int sig = 1 << (ls - 7);
        #pragma unroll
        for (int j = 0; j < 4; j++) {
            int eL = ((j >> (ls - 7)) << (ls - 7 + 1)) | (j & (sig - 1));
            float4 w = tw4[ls * 512 + qidx(t + 128 * eL, ls)];
            tC[ls-7][j][0] = w.x; tC[ls-7][j][1] = w.y; tC[ls-7][j][2] = w.z; tC[ls-7][j][3] = w.w;
        }
    }

    // packed bias for O3 ownership p = t + 128e (folded into O3's last stage)
    ull bv2[8];
    #pragma unroll
    for (int e = 0; e < 8; e++) bv2[e] = bc2(bias[t + 128 * e]);

    // ---- mbarrier init (count=1: only the elected thread arrives) ----
    if (t == 0) {
        #pragma unroll
        for (int b = 0; b < 3; b++)
            asm volatile("mbarrier.init.shared::cta.b64 [%0], 1;"
                         :: "r"(mbar_base + b * 8) : "memory");
    }
    __syncthreads();

    // ---- bulk staging: one 16KB cp.async.bulk per group ----
    auto stage = [&](int gg, int b) {
        if (t == 0 && gg < NGROUPS_TOTAL) {
            unsigned mb = mbar_base + b * 8;
            asm volatile("mbarrier.arrive.expect_tx.shared::cta.b64 _, [%0], %1;"
                         :: "r"(mb), "r"(16384) : "memory");
            asm volatile(
                "cp.async.bulk.shared::cta.global.mbarrier::complete_tx::bytes "
                "[%0], [%1], %2, [%3];"
                :: "r"(xin_base + b * 16384),
                   "l"(x + (size_t)gg * 4096),
                   "r"(16384), "r"(mb) : "memory");
        }
    };

    // ---- prologue: stage first two groups (prefetch distance 2) ----
    const int g0 = blockIdx.x;
    stage(g0, 0);
    stage(g0 + GRID, 1);

    int par = 0, phase = 0, db = 0;
    for (int g = g0; g < NGROUPS_TOTAL; g += GRID) {
        int nb = par + 2; if (nb >= 3) nb -= 3;
        stage(g + 2 * GRID, nb);

        // wait for this group's bulk copy to land
        mbar_wait(mbar_base + par * 8, phase);

        // input unpack (linear layout: row r at offset r*4KB); O1 ownership
        ull D[2][8];
        #pragma unroll
        for (int c = 0; c < 2; c++) {
            const float4* s0 = &xin[(par * 4 + 2 * c    ) * 256 + 2 * t];
            const float4* s1 = &xin[(par * 4 + 2 * c + 1) * 256 + 2 * t];
            float4 a0 = s0[0], a1 = s0[1];
            float4 b0 = s1[0], b1 = s1[1];
            D[c][0] = pk2(a0.x, b0.x);  D[c][1] = pk2(a0.y, b0.y);
            D[c][2] = pk2(a0.z, b0.z);  D[c][3] = pk2(a0.w, b0.w);
            D[c][4] = pk2(a1.x, b1.x);  D[c][5] = pk2(a1.y, b1.y);
            D[c][6] = pk2(a1.z, b1.z);  D[c][7] = pk2(a1.w, b1.w);
        }
        if (++par >= 3) { par = 0; phase ^= 1; }

        // O1: stages 1,2,4 (intra-thread, e bits 0-2)
        #pragma unroll
        for (int ls = 0; ls < 3; ls++) {
            const int s = 1 << ls;
            #pragma unroll
            for (int j = 0; j < 4; j++) {
                const int eL = ((j >> ls) << (ls + 1)) | (j & (s - 1));
                const int eH = eL + s;
                ull t00 = bc2(tA[ls][j][0]), t01 = bc2(tA[ls][j][1]);
                ull t10 = bc2(tA[ls][j][2]), t11 = bc2(tA[ls][j][3]);
                #pragma unroll
                for (int c = 0; c < 2; c++) {
                    ull x0 = D[c][eL], x1 = D[c][eH];
                    D[c][eL] = fma2(t00, x0, mul2(t01, x1));
                    D[c][eH] = fma2(t10, x0, mul2(t11, x1));
                }
            }
        }

        // ---- transpose 1: WARP-LOCAL (bufT1 region per warp is private) ----
        #pragma unroll
        for (int e = 0; e < 8; e++) {
            int p = 8 * t + e;
            float2 v0 = up2(D[0][e]), v1 = up2(D[1][e]);
            bufT1[phys(p)] = make_float4(v0.x, v0.y, v1.x, v1.y);
        }
        __syncwarp();
        #pragma unroll
        for (int e = 0; e < 8; e++) {
            float4 f = bufT1[phys(o2p(t, e))];
            D[0][e] = pk2(f.x, f.y);
            D[1][e] = pk2(f.z, f.w);
        }

        // O2: stages 8,16,32 (intra-thread, e bits = p bits 3-5)
        #pragma unroll
        for (int ls = 3; ls < 6; ls++) {
            const int sig = 1 << (ls - 3);
            #pragma unroll
            for (int j = 0; j < 4; j++) {
                const int eL = ((j >> (ls - 3)) << (ls - 3 + 1)) | (j & (sig - 1));
                const int eH = eL + sig;
                ull t00 = bc2(tB[ls-3][j][0]), t01 = bc2(tB[ls-3][j][1]);
                ull t10 = bc2(tB[ls-3][j][2]), t11 = bc2(tB[ls-3][j][3]);
                #pragma unroll
                for (int c = 0; c < 2; c++) {
                    ull x0 = D[c][eL], x1 = D[c][eH];
                    D[c][eL] = fma2(t00, x0, mul2(t01, x1));
                    D[c][eH] = fma2(t10, x0, mul2(t11, x1));
                }
            }
        }

        // stage 64: ONE shfl stage (p bit 6 = t bit 3 -> lane^8)
        #pragma unroll
        for (int c = 0; c < 2; c++)
            #pragma unroll
            for (int e = 0; e < 8; e++) {
                ull o = __shfl_xor_sync(0xffffffffu, D[c][e], 8);
                D[c][e] = fma2(bc2(tS[e][0]), D[c][e], mul2(bc2(tS[e][1]), o));
            }

        // ---- transpose 2: CTA-wide, double-buffered, single barrier ----
        float4* tb2 = bufT2 + db * BUF_F4;
        #pragma unroll
        for (int e = 0; e < 8; e++) {
            float2 v0 = up2(D[0][e]), v1 = up2(D[1][e]);
            tb2[phys(o2p(t, e))] = make_float4(v0.x, v0.y, v1.x, v1.y);
        }
        __syncthreads();                     // the ONLY CTA barrier per iter
        #pragma unroll
        for (int e = 0; e < 8; e++) {
            float4 f = tb2[phys(t + 128 * e)];
            D[0][e] = pk2(f.x, f.y);
            D[1][e] = pk2(f.z, f.w);
        }
        db ^= 1;

        // O3: stages 128,256 (intra-thread, e bits = p bits 7-9)
        #pragma unroll
        for (int ls = 7; ls < 9; ls++) {
            const int sig = 1 << (ls - 7);
            #pragma unroll
            for (int j = 0; j < 4; j++) {
                const int eL = ((j >> (ls - 7)) << (ls - 7 + 1)) | (j & (sig - 1));
                const int eH = eL + sig;
                ull t00 = bc2(tC[ls-7][j][0]), t01 = bc2(tC[ls-7][j][1]);
                ull t10 = bc2(tC[ls-7][j][2]), t11 = bc2(tC[ls-7][j][3]);
                #pragma unroll
                for (int c = 0; c < 2; c++) {
                    ull x0 = D[c][eL], x1 = D[c][eH];
                    D[c][eL] = fma2(t00, x0, mul2(t01, x1));
                    D[c][eH] = fma2(t10, x0, mul2(t11, x1));
                }
            }
        }
        // final stage 512 with bias folded into the inner fma
        #pragma unroll
        for (int j = 0; j < 4; j++) {
            const int eL = j;            // sig=4: eL = j, eH = j+4
            const int eH = j + 4;
            ull t00 = bc2(tC[2][j][0]), t01 = bc2(tC[2][j][1]);
            ull t10 = bc2(tC[2][j][2]), t11 = bc2(tC[2][j][3]);
            #pragma unroll
            for (int c = 0; c < 2; c++) {
                ull x0 = D[c][eL], x1 = D[c][eH];
                D[c][eL] = fma2(t00, x0, fma2(t01, x1, bv2[eL]));
                D[c][eH] = fma2(t10, x0, fma2(t11, x1, bv2[eH]));
            }
        }

        // epilogue: coalesced streaming stores (bias already applied)
        #pragma unroll
        for (int c = 0; c < 2; c++) {
            float* o0 = out + (size_t)(g * 4 + 2 * c    ) * 1024;
            float* o1 = out + (size_t)(g * 4 + 2 * c + 1) * 1024;
            #pragma unroll
            for (int e = 0; e < 8; e++) {
                float2 v = up2(D[c][e]);
                int p = t + 128 * e;
                __stcs(o0 + p, v.x);
                __stcs(o1 + p, v.y);
            }
        }
    }
}

extern "C" void kernel_launch(void* const* d_in, const int* in_sizes, int n_in,
                              void* d_out, int out_size) {
    const float* x    = (const float*)d_in[0];   // [32768, 1024]
    const float* tw   = (const float*)d_in[1];   // [1,1,10,512,2,2]
    const float* bias = (const float*)d_in[2];   // [1024]
    float* out = (float*)d_out;

    cudaFuncSetAttribute(butterfly_main,
                         cudaFuncAttributeMaxDynamicSharedMemorySize, SMEM_DYN);
    butterfly_main<<<GRID, 128, SMEM_DYN>>>(x, tw, bias, out);
}